// round 8
// baseline (speedup 1.0000x reference)
#include <cuda_runtime.h>
#include <cuda_fp16.h>
#include <cstdint>

// FeaturesLoss: mma.sync m16n8k16 fp16 (fp32 accum), 128x256 CTA tiles
// (64x64/warp), fp16 pre-converted features, cp.async 2-chunk K pipeline,
// ordered-pair (j>i, x2) triangular coverage, deterministic reduction.

#define BN    8192
#define DIM   128
#define TM    128                   // CTA tile rows (i)
#define TNJ   256                   // CTA tile cols (j)
#define NBLK2 1056                  // sum over bi of (32 - bi/2)
#define MARGIN 2.0f

#define NCHUNK 2                    // K chunks of 64
#define RPITCH 144                  // bytes/row/chunk: 64 fp16 = 128B + 16B pad
#define ACH    (TM  * RPITCH)       // 18432
#define BCH    (TNJ * RPITCH)       // 36864
#define SM_A   0
#define SM_B   (NCHUNK * ACH)                       // 36864
#define SM_STG (SM_B + NCHUNK * BCH)                // 110592
#define SM_SQI (SM_STG)
#define SM_SQJ (SM_SQI + TM * 4)
#define SM_LBI (SM_SQJ + TNJ * 4)
#define SM_LBJ (SM_LBI + TM * 4)
#define SM_TOT (SM_LBJ + TNJ * 4)                   // 113664

__device__ float      g_sq[BN];
__device__ int        g_lab[BN];
__device__ uint32_t   g_f16[BN * DIM / 2];          // packed half2, row-major
__device__ float      g_partials[NBLK2];
__device__ long long  g_poscnt[NBLK2];

__device__ __forceinline__ uint32_t smem_u32(const void* p) {
    uint32_t a;
    asm("{ .reg .u64 t; cvta.to.shared.u64 t, %1; cvt.u32.u64 %0, t; }" : "=r"(a) : "l"(p));
    return a;
}
__device__ __forceinline__ void cp16(uint32_t dst, const void* src) {
    asm volatile("cp.async.cg.shared.global [%0], [%1], 16;" :: "r"(dst), "l"(src));
}
__device__ __forceinline__ void cp_commit() {
    asm volatile("cp.async.commit_group;" ::: "memory");
}
template<int N> __device__ __forceinline__ void cp_wait() {
    asm volatile("cp.async.wait_group %0;" :: "n"(N) : "memory");
}
__device__ __forceinline__ void mma_f16(float c[4], uint32_t a0, uint32_t a1,
                                        uint32_t a2, uint32_t a3,
                                        uint32_t b0, uint32_t b1) {
    asm volatile(
        "mma.sync.aligned.m16n8k16.row.col.f32.f16.f16.f32 "
        "{%0,%1,%2,%3}, {%4,%5,%6,%7}, {%8,%9}, {%0,%1,%2,%3};"
        : "+f"(c[0]), "+f"(c[1]), "+f"(c[2]), "+f"(c[3])
        : "r"(a0), "r"(a1), "r"(a2), "r"(a3), "r"(b0), "r"(b1));
}

// ---------------------------------------------------------------------------
// Kernel 0: squared norms (exact fp32), label conversion, fp16 feature copy.
// ---------------------------------------------------------------------------
__global__ void prep_kernel(const float* __restrict__ F,
                            const void* __restrict__ labels_raw) {
    int warp = (blockIdx.x * blockDim.x + threadIdx.x) >> 5;
    int lane = threadIdx.x & 31;
    if (warp >= BN) return;

    const int* w = (const int*)labels_raw;
    int probe = w[2 * lane + 1];
    unsigned is64 = __all_sync(0xffffffffu, probe == 0);

    const float4* row = (const float4*)(F + (size_t)warp * DIM);
    float4 f = row[lane];

    // fp16 copy (packed half2 pairs, natural k order)
    __half2 h0 = __floats2half2_rn(f.x, f.y);
    __half2 h1 = __floats2half2_rn(f.z, f.w);
    uint2 hp = { *(uint32_t*)&h0, *(uint32_t*)&h1 };
    *(uint2*)&g_f16[(size_t)warp * 64 + lane * 2] = hp;

    float s = f.x * f.x + f.y * f.y + f.z * f.z + f.w * f.w;
    #pragma unroll
    for (int off = 16; off; off >>= 1)
        s += __shfl_xor_sync(0xffffffffu, s, off);

    if (lane == 0) {
        g_sq[warp] = s;
        int lab;
        if (is64) lab = (int)((const long long*)labels_raw)[warp];
        else      lab = w[warp];
        g_lab[warp] = lab;
    }
}

// ---------------------------------------------------------------------------
// Kernel 1: one 128x256 pair tile per CTA; pairs counted iff gj > gi (x2).
// ---------------------------------------------------------------------------
__global__ void __launch_bounds__(256, 1)
tile_kernel() {
    extern __shared__ char smem[];
    uint32_t sbase = smem_u32(smem);

    int t = threadIdx.x;
    int wid = t >> 5, lane = t & 31;
    int gid = lane >> 2, tig = lane & 3;

    // block id -> (bi, bjp); col-pair bjp covers j in [bjp*256, +256), bjp >= bi/2
    int idx = blockIdx.x;
    int bi = 0;
    while (idx >= 32 - (bi >> 1)) { idx -= 32 - (bi >> 1); bi++; }
    int bjp = (bi >> 1) + idx;
    int i0 = bi * TM, j0 = bjp * TNJ;

    const char* f16b = (const char*)g_f16;   // 256 B per feature row

    // issue both K-chunks as separate commit groups (chunk c = k [64c, 64c+64))
    #pragma unroll
    for (int c = 0; c < NCHUNK; c++) {
        #pragma unroll
        for (int s = t; s < TM * 8; s += 256) {       // A: 1024 16B segs
            int r = s >> 3, q = s & 7;
            cp16(sbase + SM_A + c * ACH + r * RPITCH + q * 16,
                 f16b + (size_t)(i0 + r) * 256 + c * 128 + q * 16);
        }
        #pragma unroll
        for (int s = t; s < TNJ * 8; s += 256) {      // B: 2048 16B segs
            int r = s >> 3, q = s & 7;
            cp16(sbase + SM_B + c * BCH + r * RPITCH + q * 16,
                 f16b + (size_t)(j0 + r) * 256 + c * 128 + q * 16);
        }
        cp_commit();
    }

    // stage sq/labels while copies fly
    float* sqI = (float*)(smem + SM_SQI);
    float* sqJ = (float*)(smem + SM_SQJ);
    int*   lbI = (int*)  (smem + SM_LBI);
    int*   lbJ = (int*)  (smem + SM_LBJ);
    if (t < TM) { sqI[t] = g_sq[i0 + t]; lbI[t] = g_lab[i0 + t]; }
    sqJ[t] = g_sq[j0 + t];  lbJ[t] = g_lab[j0 + t];   // TNJ == 256 == blockDim

    int wm = wid & 1;            // row block of 64
    int wn = wid >> 1;           // col block of 64
    int mbase = wm * 64;
    int nbase = wn * 64;

    float acc[4][8][4];
    #pragma unroll
    for (int mf = 0; mf < 4; mf++)
        #pragma unroll
        for (int nf = 0; nf < 8; nf++)
            #pragma unroll
            for (int rr = 0; rr < 4; rr++) acc[mf][nf][rr] = 0.0f;

    // K loop: 2 chunks x 4 k16-steps  (row = 36 uint32; k16 = 8 uint32)
    #pragma unroll
    for (int c = 0; c < NCHUNK; c++) {
        if (c == 0) cp_wait<1>();
        else        cp_wait<0>();
        __syncthreads();

        const uint32_t* Ac = (const uint32_t*)(smem + SM_A + c * ACH);
        const uint32_t* Bc = (const uint32_t*)(smem + SM_B + c * BCH);

        #pragma unroll
        for (int kk = 0; kk < 4; kk++) {
            int kb = kk * 8;
            uint32_t a[4][4];
            #pragma unroll
            for (int mf = 0; mf < 4; mf++) {
                const uint32_t* r0 = Ac + (size_t)(mbase + 16 * mf + gid) * 36 + kb;
                const uint32_t* r1 = Ac + (size_t)(mbase + 16 * mf + gid + 8) * 36 + kb;
                a[mf][0] = r0[tig];
                a[mf][1] = r1[tig];
                a[mf][2] = r0[tig + 4];
                a[mf][3] = r1[tig + 4];
            }
            uint32_t b[8][2];
            #pragma unroll
            for (int nf = 0; nf < 8; nf++) {
                const uint32_t* rn = Bc + (size_t)(nbase + 8 * nf + gid) * 36 + kb;
                b[nf][0] = rn[tig];
                b[nf][1] = rn[tig + 4];
            }
            #pragma unroll
            for (int mf = 0; mf < 4; mf++)
                #pragma unroll
                for (int nf = 0; nf < 8; nf++)
                    mma_f16(acc[mf][nf], a[mf][0], a[mf][1], a[mf][2], a[mf][3],
                            b[nf][0], b[nf][1]);
        }
    }

    // ---- fused epilogue: ordered pairs gj > gi, weight x2 ----
    float lsum = 0.0f;
    int   lcnt = 0;
    #pragma unroll
    for (int mf = 0; mf < 4; mf++) {
        #pragma unroll
        for (int rr = 0; rr < 2; rr++) {
            int m  = mbase + 16 * mf + gid + 8 * rr;
            int gi = i0 + m;
            float sqi = sqI[m];
            int   li  = lbI[m];
            #pragma unroll
            for (int nf = 0; nf < 8; nf++) {
                #pragma unroll
                for (int cc = 0; cc < 2; cc++) {
                    int n  = nbase + 8 * nf + tig * 2 + cc;
                    int gj = j0 + n;
                    if (gj <= gi) continue;
                    float dot = acc[mf][nf][rr * 2 + cc];
                    float d2 = fmaxf(sqi + sqJ[n] - 2.0f * dot, 0.0f);
                    if (li == lbJ[n]) {
                        lsum += d2;
                        lcnt++;
                    } else if (d2 < MARGIN * MARGIN) {   // ~never taken (8 sigma)
                        float h = MARGIN - sqrtf(d2);
                        lsum += h * h;
                    }
                }
            }
        }
    }

    // deterministic block reduction
    #pragma unroll
    for (int off = 16; off; off >>= 1) {
        lsum += __shfl_xor_sync(0xffffffffu, lsum, off);
        lcnt += __shfl_xor_sync(0xffffffffu, lcnt, off);
    }
    __shared__ float rbuf[8];
    __shared__ int   rcnt[8];
    if (lane == 0) { rbuf[wid] = lsum; rcnt[wid] = lcnt; }
    __syncthreads();
    if (t == 0) {
        float s = 0.0f; long long c = 0;
        #pragma unroll
        for (int wd = 0; wd < 8; wd++) { s += rbuf[wd]; c += rcnt[wd]; }
        g_partials[blockIdx.x] = s * 2.0f;
        g_poscnt[blockIdx.x]   = c * 2LL;
    }
}

// ---------------------------------------------------------------------------
__global__ void finalize_kernel(float* __restrict__ out) {
    int t = threadIdx.x;
    double s = 0.0; long long c = 0;
    for (int i = t; i < NBLK2; i += 256) {
        s += (double)g_partials[i];
        c += g_poscnt[i];
    }
    __shared__ double    sd[256];
    __shared__ long long sc[256];
    sd[t] = s; sc[t] = c;
    __syncthreads();
    for (int off = 128; off; off >>= 1) {
        if (t < off) { sd[t] += sd[t + off]; sc[t] += sc[t + off]; }
        __syncthreads();
    }
    if (t == 0) {
        double total = sd[0];
        double denom = (double)((long long)BN * (BN - 1));
        out[0] = (float)(sc[0] > 0 ? total / denom : total);
    }
}

// ---------------------------------------------------------------------------
extern "C" void kernel_launch(void* const* d_in, const int* in_sizes, int n_in,
                              void* d_out, int out_size) {
    const float* F      = (const float*)d_in[0];
    const void*  labels = d_in[1];
    float*       out    = (float*)d_out;

    cudaFuncSetAttribute(tile_kernel,
                         cudaFuncAttributeMaxDynamicSharedMemorySize, SM_TOT);

    prep_kernel<<<BN / 8, 256>>>(F, labels);
    tile_kernel<<<NBLK2, 256, SM_TOT>>>();
    finalize_kernel<<<1, 256>>>(out);
}

// round 9
// speedup vs baseline: 1.2426x; 1.2426x over previous
#include <cuda_runtime.h>
#include <cstdint>

// FeaturesLoss: mma.sync m16n8k8 tf32, persistent CTAs with dynamic tile
// tickets, cross-tile cp.async 4-chunk ring pipeline, 128x256 tiles
// (64x64/warp), ordered-pair (j>i, x2) coverage, deterministic reduction.

#define BN    8192
#define DIM   128
#define TM    128
#define TNJ   256
#define NBLK2 1056                  // sum over bi of (32 - bi/2)
#define MARGIN 2.0f
#define NPERS 152                   // persistent CTAs (GB300: 152 SMs)

#define CH     32                   // K floats per chunk
#define NCHUNK 4
#define RPITCH 144                  // bytes per row per chunk (36 floats)
#define ACH    (TM  * RPITCH)       // 18432
#define BCH    (TNJ * RPITCH)       // 36864
#define SM_A   0
#define SM_B   (NCHUNK * ACH)                       // 73728
#define SM_STG (SM_B + NCHUNK * BCH)                // 221184
#define STGSZ  3072                                 // per-parity staging bytes
#define SM_TOT (SM_STG + 2 * STGSZ)                 // 227328

__device__ float      g_sq[BN];
__device__ int        g_lab[BN];
__device__ float      g_partials[NBLK2];
__device__ long long  g_poscnt[NBLK2];
__device__ unsigned   g_ticket;

__device__ __forceinline__ uint32_t smem_u32(const void* p) {
    uint32_t a;
    asm("{ .reg .u64 t; cvta.to.shared.u64 t, %1; cvt.u32.u64 %0, t; }" : "=r"(a) : "l"(p));
    return a;
}
__device__ __forceinline__ void cp16(uint32_t dst, const void* src) {
    asm volatile("cp.async.cg.shared.global [%0], [%1], 16;" :: "r"(dst), "l"(src));
}
__device__ __forceinline__ void cp_commit() {
    asm volatile("cp.async.commit_group;" ::: "memory");
}
template<int N> __device__ __forceinline__ void cp_wait() {
    asm volatile("cp.async.wait_group %0;" :: "n"(N) : "memory");
}
__device__ __forceinline__ void mma_tf32(float c[4], uint32_t a0, uint32_t a1,
                                         uint32_t a2, uint32_t a3,
                                         uint32_t b0, uint32_t b1) {
    asm volatile(
        "mma.sync.aligned.m16n8k8.row.col.f32.tf32.tf32.f32 "
        "{%0,%1,%2,%3}, {%4,%5,%6,%7}, {%8,%9}, {%0,%1,%2,%3};"
        : "+f"(c[0]), "+f"(c[1]), "+f"(c[2]), "+f"(c[3])
        : "r"(a0), "r"(a1), "r"(a2), "r"(a3), "r"(b0), "r"(b1));
}
__device__ __forceinline__ void decode_tile(int idx, int& i0, int& j0) {
    int bi = 0;
    while (idx >= 32 - (bi >> 1)) { idx -= 32 - (bi >> 1); bi++; }
    i0 = bi * TM;
    j0 = ((bi >> 1) + idx) * TNJ;
}

// ---------------------------------------------------------------------------
__global__ void prep_kernel(const float* __restrict__ F,
                            const void* __restrict__ labels_raw) {
    if (blockIdx.x == 0 && threadIdx.x == 0) g_ticket = 0;  // reset per replay

    int warp = (blockIdx.x * blockDim.x + threadIdx.x) >> 5;
    int lane = threadIdx.x & 31;
    if (warp >= BN) return;

    const int* w = (const int*)labels_raw;
    int probe = w[2 * lane + 1];
    unsigned is64 = __all_sync(0xffffffffu, probe == 0);

    const float4* row = (const float4*)(F + (size_t)warp * DIM);
    float4 f = row[lane];
    float s = f.x * f.x + f.y * f.y + f.z * f.z + f.w * f.w;
    #pragma unroll
    for (int off = 16; off; off >>= 1)
        s += __shfl_xor_sync(0xffffffffu, s, off);

    if (lane == 0) {
        g_sq[warp] = s;
        int lab;
        if (is64) lab = (int)((const long long*)labels_raw)[warp];
        else      lab = w[warp];
        g_lab[warp] = lab;
    }
}

// ---------------------------------------------------------------------------
// Issue cp.async for one K-chunk of one tile into ring buffer c.
__device__ __forceinline__ void issue_chunk(uint32_t sbase, const float* F,
                                            int i0, int j0, int c, int t) {
    #pragma unroll
    for (int s = t; s < TM * 8; s += 256) {       // A: 1024 16B segs
        int r = s >> 3, q = s & 7;
        cp16(sbase + SM_A + c * ACH + r * RPITCH + q * 16,
             F + (size_t)(i0 + r) * DIM + c * CH + q * 4);
    }
    #pragma unroll
    for (int s = t; s < TNJ * 8; s += 256) {      // B: 2048 16B segs
        int r = s >> 3, q = s & 7;
        cp16(sbase + SM_B + c * BCH + r * RPITCH + q * 16,
             F + (size_t)(j0 + r) * DIM + c * CH + q * 4);
    }
}

// ---------------------------------------------------------------------------
__global__ void __launch_bounds__(256, 1)
tile_kernel(const float* __restrict__ F) {
    extern __shared__ char smem[];
    uint32_t sbase = smem_u32(smem);

    int t = threadIdx.x;
    int wid = t >> 5, lane = t & 31;
    int gid = lane >> 2, tig = lane & 3;
    int wm = wid & 1, wn = wid >> 1;
    int mbase = wm * 64, nbase = wn * 64;

    __shared__ int s_tick;
    __shared__ float rbuf[8];
    __shared__ int   rcnt[8];

    if (t == 0) s_tick = (int)atomicAdd(&g_ticket, 1u);
    __syncthreads();
    int cur = s_tick;
    if (cur >= NBLK2) return;

    int i0, j0;
    decode_tile(cur, i0, j0);

    // prologue: fill all 4 chunk buffers for the first tile
    #pragma unroll
    for (int c = 0; c < NCHUNK; c++) {
        issue_chunk(sbase, F, i0, j0, c, t);
        cp_commit();
    }

    int parity = 0;
    for (;;) {
        // grab next ticket + stage sq/labels for current tile
        if (t == 0) s_tick = (int)atomicAdd(&g_ticket, 1u);
        {
            char* stg = smem + SM_STG + parity * STGSZ;
            float* sqI = (float*)stg;
            float* sqJ = (float*)(stg + 512);
            int*   lbI = (int*)  (stg + 1536);
            int*   lbJ = (int*)  (stg + 2048);
            if (t < TM) { sqI[t] = g_sq[i0 + t]; lbI[t] = g_lab[i0 + t]; }
            sqJ[t] = g_sq[j0 + t];
            lbJ[t] = g_lab[j0 + t];
        }
        __syncthreads();
        int nxt = s_tick;
        int ni0 = 0, nj0 = 0;
        bool more = (nxt < NBLK2);
        if (more) decode_tile(nxt, ni0, nj0);

        float acc[4][8][4];
        #pragma unroll
        for (int mf = 0; mf < 4; mf++)
            #pragma unroll
            for (int nf = 0; nf < 8; nf++)
                #pragma unroll
                for (int rr = 0; rr < 4; rr++) acc[mf][nf][rr] = 0.0f;

        // K loop over ring: compute chunk c, then refill it with next tile's c
        #pragma unroll
        for (int c = 0; c < NCHUNK; c++) {
            cp_wait<3>();
            __syncthreads();

            const float* Ac = (const float*)(smem + SM_A + c * ACH);
            const float* Bc = (const float*)(smem + SM_B + c * BCH);

            #pragma unroll
            for (int k8 = 0; k8 < 4; k8++) {
                int kb = k8 * 8;
                uint32_t a[4][4];
                #pragma unroll
                for (int mf = 0; mf < 4; mf++) {
                    const uint32_t* r0 = (const uint32_t*)(Ac + (size_t)(mbase + 16 * mf + gid) * 36 + kb);
                    const uint32_t* r1 = (const uint32_t*)(Ac + (size_t)(mbase + 16 * mf + gid + 8) * 36 + kb);
                    a[mf][0] = r0[tig];
                    a[mf][1] = r1[tig];
                    a[mf][2] = r0[tig + 4];
                    a[mf][3] = r1[tig + 4];
                }
                uint32_t b[8][2];
                #pragma unroll
                for (int nf = 0; nf < 8; nf++) {
                    const uint32_t* rn = (const uint32_t*)(Bc + (size_t)(nbase + 8 * nf + gid) * 36 + kb);
                    b[nf][0] = rn[tig];
                    b[nf][1] = rn[tig + 4];
                }
                #pragma unroll
                for (int mf = 0; mf < 4; mf++)
                    #pragma unroll
                    for (int nf = 0; nf < 8; nf++)
                        mma_tf32(acc[mf][nf], a[mf][0], a[mf][1], a[mf][2], a[mf][3],
                                 b[nf][0], b[nf][1]);
            }

            __syncthreads();              // all warps done reading buffer c
            if (more) issue_chunk(sbase, F, ni0, nj0, c, t);
            cp_commit();                  // commit (possibly empty) to keep FIFO
        }

        // ---- fused epilogue: ordered pairs gj > gi, weight x2 ----
        const char* stg = smem + SM_STG + parity * STGSZ;
        const float* sqI = (const float*)stg;
        const float* sqJ = (const float*)(stg + 512);
        const int*   lbI = (const int*)  (stg + 1536);
        const int*   lbJ = (const int*)  (stg + 2048);

        float lsum = 0.0f;
        int   lcnt = 0;
        #pragma unroll
        for (int mf = 0; mf < 4; mf++) {
            #pragma unroll
            for (int rr = 0; rr < 2; rr++) {
                int m  = mbase + 16 * mf + gid + 8 * rr;
                int gi = i0 + m;
                float sqi = sqI[m];
                int   li  = lbI[m];
                #pragma unroll
                for (int nf = 0; nf < 8; nf++) {
                    #pragma unroll
                    for (int cc = 0; cc < 2; cc++) {
                        int n  = nbase + 8 * nf + tig * 2 + cc;
                        int gj = j0 + n;
                        if (gj <= gi) continue;
                        float dot = acc[mf][nf][rr * 2 + cc];
                        float d2 = fmaxf(sqi + sqJ[n] - 2.0f * dot, 0.0f);
                        if (li == lbJ[n]) {
                            lsum += d2;
                            lcnt++;
                        } else if (d2 < MARGIN * MARGIN) {   // ~never (8 sigma)
                            float h = MARGIN - sqrtf(d2);
                            lsum += h * h;
                        }
                    }
                }
            }
        }

        #pragma unroll
        for (int off = 16; off; off >>= 1) {
            lsum += __shfl_xor_sync(0xffffffffu, lsum, off);
            lcnt += __shfl_xor_sync(0xffffffffu, lcnt, off);
        }
        if (lane == 0) { rbuf[wid] = lsum; rcnt[wid] = lcnt; }
        __syncthreads();
        if (t == 0) {
            float s = 0.0f; long long c = 0;
            #pragma unroll
            for (int wd = 0; wd < 8; wd++) { s += rbuf[wd]; c += rcnt[wd]; }
            g_partials[cur] = s * 2.0f;
            g_poscnt[cur]   = c * 2LL;
        }

        if (!more) break;
        cur = nxt; i0 = ni0; j0 = nj0; parity ^= 1;
    }
}

// ---------------------------------------------------------------------------
__global__ void finalize_kernel(float* __restrict__ out) {
    int t = threadIdx.x;
    double s = 0.0; long long c = 0;
    for (int i = t; i < NBLK2; i += 256) {
        s += (double)g_partials[i];
        c += g_poscnt[i];
    }
    __shared__ double    sd[256];
    __shared__ long long sc[256];
    sd[t] = s; sc[t] = c;
    __syncthreads();
    for (int off = 128; off; off >>= 1) {
        if (t < off) { sd[t] += sd[t + off]; sc[t] += sc[t + off]; }
        __syncthreads();
    }
    if (t == 0) {
        double total = sd[0];
        double denom = (double)((long long)BN * (BN - 1));
        out[0] = (float)(sc[0] > 0 ? total / denom : total);
    }
}

// ---------------------------------------------------------------------------
extern "C" void kernel_launch(void* const* d_in, const int* in_sizes, int n_in,
                              void* d_out, int out_size) {
    const float* F      = (const float*)d_in[0];
    const void*  labels = d_in[1];
    float*       out    = (float*)d_out;

    cudaFuncSetAttribute(tile_kernel,
                         cudaFuncAttributeMaxDynamicSharedMemorySize, SM_TOT);

    prep_kernel<<<BN / 8, 256>>>(F, labels);
    tile_kernel<<<NPERS, 256, SM_TOT>>>(F);
    finalize_kernel<<<1, 256>>>(out);
}